// round 8
// baseline (speedup 1.0000x reference)
#include <cuda_runtime.h>
#include <cstdint>

#define NB 32
#define NT 1024
#define ND 512
#define NU 512

// 64MB scratch for xw = x @ kernel   (static __device__ — no allocation)
__device__ float g_xw[NB * NT * NU];

// ---------------- f32x2 packed helpers ----------------
__device__ __forceinline__ unsigned long long pk2(float x, float y) {
    unsigned long long r;
    asm("mov.b64 %0, {%1, %2};" : "=l"(r) : "f"(x), "f"(y));
    return r;
}
__device__ __forceinline__ unsigned long long pk2s(float x) {
    unsigned long long r;
    asm("mov.b64 %0, {%1, %1};" : "=l"(r) : "f"(x));
    return r;
}
__device__ __forceinline__ void fma2(unsigned long long& d, unsigned long long a,
                                     unsigned long long b) {
    asm("fma.rn.f32x2 %0, %1, %2, %0;" : "+l"(d) : "l"(a), "l"(b));
}
__device__ __forceinline__ float2 upk2(unsigned long long a) {
    float2 r;
    asm("mov.b64 {%0, %1}, %2;" : "=f"(r.x), "=f"(r.y) : "l"(a));
    return r;
}

// ======================================================================
// Kernel 1: XW = X[32768,512] @ W[512,512], fp32, f32x2-packed SIMT GEMM
// ======================================================================
__global__ __launch_bounds__(256) void xw_gemm(const float* __restrict__ X,
                                               const float* __restrict__ W) {
    __shared__ float As[8][128];
    __shared__ float Bs[8][128];

    const int tid = threadIdx.x;
    const int m0 = blockIdx.y * 128;
    const int n0 = blockIdx.x * 128;

    const int ar = tid >> 1;
    const int ac = (tid & 1) * 4;
    const int br = tid >> 5;
    const int bc = (tid & 31) * 4;

    const int tx = tid & 15;
    const int ty = tid >> 4;

    unsigned long long acc[8][4];
#pragma unroll
    for (int i = 0; i < 8; i++)
#pragma unroll
        for (int j = 0; j < 4; j++) acc[i][j] = 0ull;

    float4 xa = *reinterpret_cast<const float4*>(&X[(size_t)(m0 + ar) * ND + ac]);
    float4 wb = *reinterpret_cast<const float4*>(&W[(size_t)br * NU + n0 + bc]);

    const int KT = ND / 8;
    for (int kt = 0; kt < KT; kt++) {
        As[ac + 0][ar] = xa.x;
        As[ac + 1][ar] = xa.y;
        As[ac + 2][ar] = xa.z;
        As[ac + 3][ar] = xa.w;
        *reinterpret_cast<float4*>(&Bs[br][bc]) = wb;
        __syncthreads();

        if (kt + 1 < KT) {
            xa = *reinterpret_cast<const float4*>(
                &X[(size_t)(m0 + ar) * ND + (kt + 1) * 8 + ac]);
            wb = *reinterpret_cast<const float4*>(
                &W[(size_t)((kt + 1) * 8 + br) * NU + n0 + bc]);
        }

#pragma unroll
        for (int k = 0; k < 8; k++) {
            float4 a0 = *reinterpret_cast<const float4*>(&As[k][ty * 8]);
            float4 a1 = *reinterpret_cast<const float4*>(&As[k][ty * 8 + 4]);
            ulonglong2 bq0 = *reinterpret_cast<const ulonglong2*>(&Bs[k][tx * 8]);
            ulonglong2 bq1 = *reinterpret_cast<const ulonglong2*>(&Bs[k][tx * 8 + 4]);
            unsigned long long bb0 = bq0.x, bb1 = bq0.y, bb2 = bq1.x, bb3 = bq1.y;
            float av[8] = {a0.x, a0.y, a0.z, a0.w, a1.x, a1.y, a1.z, a1.w};
#pragma unroll
            for (int i = 0; i < 8; i++) {
                unsigned long long aa = pk2s(av[i]);
                fma2(acc[i][0], aa, bb0);
                fma2(acc[i][1], aa, bb1);
                fma2(acc[i][2], aa, bb2);
                fma2(acc[i][3], aa, bb3);
            }
        }
        __syncthreads();
    }

#pragma unroll
    for (int i = 0; i < 8; i++) {
        size_t row = (size_t)(m0 + ty * 8 + i);
        float2* op = reinterpret_cast<float2*>(&g_xw[row * NU + n0 + tx * 8]);
        op[0] = upk2(acc[i][0]);
        op[1] = upk2(acc[i][1]);
        op[2] = upk2(acc[i][2]);
        op[3] = upk2(acc[i][3]);
    }
}

// ======================================================================
// Kernel 2: sequential scan  h_t = xw_t + h_{t-1} @ R
// 16 clusters x 8 CTAs; each CTA owns 64 units of both cluster batches.
// Two INDEPENDENT per-batch chains, each with its own mbarrier pair and
// send point -> each chain's DSMEM latency hides under the other's compute.
// Reduction is shuffle-only: lane = (unit octet, k-quarter); no smem reduce.
// ======================================================================
__global__ __launch_bounds__(256, 1) __cluster_dims__(8, 1, 1)
void scan_kernel(const float* __restrict__ Rm, float* __restrict__ out) {
    __shared__ alignas(16) float hbuf[2][2][NU];      // [parity][chain][unit] 8KB
    __shared__ alignas(8) unsigned long long mbar[2][2];  // [chain][parity]

    const int tid = threadIdx.x;
    uint32_t rank;
    asm("mov.u32 %0, %%cluster_ctarank;" : "=r"(rank));
    const int cluster = blockIdx.x >> 3;
    const int b0 = cluster * 2;

    const int w = tid >> 5;              // warp 0..7
    const int lane = tid & 31;
    const int ksub = lane >> 3;          // k-quarter 0..3
    const int ul = lane & 7;             // unit within octet
    const int ulocal = w * 8 + ul;       // 0..63 (this CTA's unit)
    const int ug = (int)rank * 64 + ulocal;  // global unit (R column)
    const int qbase = ksub * 128;        // k-quarter start
    const int rot = ksub * 8;            // bank-derotation phase (floats)

    // ---- R column slice into registers: quarter of column ug, rotated ----
    // Rp[2i]   = {R[k][ug],   R[k+1][ug]},  Rp[2i+1] = {R[k+2][ug], R[k+3][ug]}
    // where k = qbase + ((i*4 + rot) & 127)
    unsigned long long Rp[64];
#pragma unroll
    for (int i = 0; i < 32; i++) {
        const int k = qbase + ((i * 4 + rot) & 127);
        const float* rb = &Rm[(size_t)k * NU + ug];
        Rp[2 * i + 0] = pk2(rb[0 * NU], rb[1 * NU]);
        Rp[2 * i + 1] = pk2(rb[2 * NU], rb[3 * NU]);
    }

    // zero h_0 buffers (both parities, both chains)
    for (int i = tid; i < 2 * 2 * NU; i += 256) (&hbuf[0][0][0])[i] = 0.f;

    // barriers: mbar[chain][parity], each expects 7 * 256B = 1792B per phase
    uint32_t barL[2][2];
#pragma unroll
    for (int c = 0; c < 2; c++)
#pragma unroll
        for (int p = 0; p < 2; p++)
            barL[c][p] = (uint32_t)__cvta_generic_to_shared(&mbar[c][p]);
    if (tid == 0) {
#pragma unroll
        for (int c = 0; c < 2; c++)
#pragma unroll
            for (int p = 0; p < 2; p++) {
                asm volatile("mbarrier.init.shared.b64 [%0], 1;" :: "r"(barL[c][p]) : "memory");
                asm volatile("mbarrier.arrive.expect_tx.shared.b64 _, [%0], %1;"
                             :: "r"(barL[c][p]), "r"(1792) : "memory");
            }
    }
    __syncthreads();
    // one-time rendezvous: inits/arms + zeroed hbuf visible before any bulk
    asm volatile("barrier.cluster.arrive.aligned;" ::: "memory");
    asm volatile("barrier.cluster.wait.aligned;" ::: "memory");

    // owners: ksub==0 lanes own output unit ulocal for both chains
    const bool owner = (ksub == 0);
    const float* xwp[2];
    float* outp[2];
#pragma unroll
    for (int c = 0; c < 2; c++) {
        xwp[c] = &g_xw[((size_t)(b0 + c) * NT) * NU + ug];
        outp[c] = &out[((size_t)(b0 + c) * NT) * NU + ug];
    }
    float xwcur[2];
    xwcur[0] = owner ? xwp[0][0] : 0.f;
    xwcur[1] = owner ? xwp[1][0] : 0.f;

    // tid0: bulk endpoints. src = own slice of local hbuf[p][c]; dst = same
    // offset in peer CTA; barrier = peer's mbar[c][p]. 7 remote dests.
    uint32_t srcA[2][2], dstA[2][2][8], mbR[2][2][8];
    if (tid == 0) {
#pragma unroll
        for (int c = 0; c < 2; c++)
#pragma unroll
            for (int p = 0; p < 2; p++) {
                uint32_t slotL =
                    (uint32_t)__cvta_generic_to_shared(&hbuf[p][c][rank * 64]);
                srcA[c][p] = slotL;
#pragma unroll
                for (int d = 0; d < 8; d++) {
                    asm("mapa.shared::cluster.u32 %0, %1, %2;"
                        : "=r"(dstA[c][p][d]) : "r"(slotL), "r"(d));
                    asm("mapa.shared::cluster.u32 %0, %1, %2;"
                        : "=r"(mbR[c][p][d]) : "r"(barL[c][p]), "r"(d));
                }
            }
    }

    int par[2][2] = {{0, 0}, {0, 0}};

    for (int t = 0; t < NT; t++) {
        const int cur = t & 1, nxt = cur ^ 1;

        // prefetch next-step xw for both chains (independent of waits)
        float xwn[2] = {0.f, 0.f};
        if (owner && (t + 1) < NT) {
            xwn[0] = xwp[0][(size_t)(t + 1) * NU];
            xwn[1] = xwp[1][(size_t)(t + 1) * NU];
        }

#pragma unroll
        for (int c = 0; c < 2; c++) {
            // ---- wait for h_c(t) ----
            if (t > 0) {
                const uint32_t ba = barL[c][cur];
                const uint32_t ph = (uint32_t)par[c][cur];
                uint32_t done;
                asm volatile(
                    "{\n\t.reg .pred p;\n\t"
                    "mbarrier.try_wait.parity.acquire.cluster.shared::cta.b64 p, [%1], %2;\n\t"
                    "selp.b32 %0, 1, 0, p;\n\t}"
                    : "=r"(done) : "r"(ba), "r"(ph) : "memory");
                while (!done) {
                    asm volatile(
                        "{\n\t.reg .pred p;\n\t"
                        "mbarrier.try_wait.parity.acquire.cluster.shared::cta.b64 p, [%1], %2, 0x989680;\n\t"
                        "selp.b32 %0, 1, 0, p;\n\t}"
                        : "=r"(done) : "r"(ba), "r"(ph) : "memory");
                }
                par[c][cur] ^= 1;
                // re-arm for step t+2 (tid0's sends follow in program order)
                if (tid == 0 && (t + 2) < NT) {
                    asm volatile("mbarrier.arrive.expect_tx.shared.b64 _, [%0], %1;"
                                 :: "r"(ba), "r"(1792) : "memory");
                }
            }

            // ---- matvec quarter: 32 x (LDS.128 broadcast -> 2 fma2) ----
            const float* hb = &hbuf[cur][c][0];
            unsigned long long a0 = 0ull, a1 = 0ull;
#pragma unroll
            for (int i = 0; i < 32; i++) {
                const int off = qbase + ((i * 4 + rot) & 127);
                ulonglong2 hp = *reinterpret_cast<const ulonglong2*>(&hb[off]);
                fma2(a0, Rp[2 * i + 0], hp.x);
                fma2(a1, Rp[2 * i + 1], hp.y);
            }
            float2 f0 = upk2(a0), f1 = upk2(a1);
            float s = (f0.x + f0.y) + (f1.x + f1.y);
            // 4-way cross-ksub reduction, shuffle-only
            s += __shfl_xor_sync(0xffffffffu, s, 8);
            s += __shfl_xor_sync(0xffffffffu, s, 16);

            if (owner) {
                const float val = xwcur[c] + s;
                outp[c][(size_t)t * NU] = val;
                if (t + 1 < NT) hbuf[nxt][c][rank * 64 + ulocal] = val;  // own slice
            }
            __syncthreads();  // slice complete (and hbuf[cur] reads done) before send

            // ---- aggregated DSMEM push: 7 x 256B bulk copies, 1 tx each ----
            if (tid == 0 && (t + 1) < NT) {
                asm volatile("fence.proxy.async.shared::cta;" ::: "memory");
#pragma unroll
                for (int d = 0; d < 8; d++) {
                    if (d != (int)rank) {
                        asm volatile(
                            "cp.async.bulk.shared::cluster.shared::cta.mbarrier::complete_tx::bytes "
                            "[%0], [%1], %2, [%3];"
                            :: "r"(dstA[c][nxt][d]), "r"(srcA[c][nxt]), "r"(256),
                               "r"(mbR[c][nxt][d])
                            : "memory");
                    }
                }
            }
        }
        xwcur[0] = xwn[0];
        xwcur[1] = xwn[1];
    }

    // final rendezvous: no CTA exits while peers could still touch its smem
    asm volatile("barrier.cluster.arrive.aligned;" ::: "memory");
    asm volatile("barrier.cluster.wait.aligned;" ::: "memory");
}

// ======================================================================
extern "C" void kernel_launch(void* const* d_in, const int* in_sizes, int n_in,
                              void* d_out, int out_size) {
    const float* x = (const float*)d_in[0];            // [32,1024,512]
    const float* W = (const float*)d_in[1];            // kernel [512,512]
    const float* R = (const float*)d_in[2];            // recurrent_kernel [512,512]
    float* out = (float*)d_out;                        // [32,1024,512]

    dim3 gg(NU / 128, (NB * NT) / 128);                // (4, 256)
    xw_gemm<<<gg, 256>>>(x, W);
    scan_kernel<<<128, 256>>>(R, out);                 // 16 clusters x 8 CTAs
}

// round 9
// speedup vs baseline: 1.4029x; 1.4029x over previous
#include <cuda_runtime.h>
#include <cstdint>

#define NB 32
#define NT 1024
#define ND 512
#define NU 512

// static scratch (no allocation): z = x@W + xshift@W2, plus W2=W@R, R2=R@R
__device__ float g_z[NB * NT * NU];     // 64MB
__device__ float g_W2[ND * NU];         // 1MB
__device__ float g_R2[NU * NU];         // 1MB

// ---------------- f32x2 packed helpers ----------------
__device__ __forceinline__ unsigned long long pk2(float x, float y) {
    unsigned long long r;
    asm("mov.b64 %0, {%1, %2};" : "=l"(r) : "f"(x), "f"(y));
    return r;
}
__device__ __forceinline__ unsigned long long pk2s(float x) {
    unsigned long long r;
    asm("mov.b64 %0, {%1, %1};" : "=l"(r) : "f"(x));
    return r;
}
__device__ __forceinline__ void fma2(unsigned long long& d, unsigned long long a,
                                     unsigned long long b) {
    asm("fma.rn.f32x2 %0, %1, %2, %0;" : "+l"(d) : "l"(a), "l"(b));
}
__device__ __forceinline__ float2 upk2(unsigned long long a) {
    float2 r;
    asm("mov.b64 {%0, %1}, %2;" : "=f"(r.x), "=f"(r.y) : "l"(a));
    return r;
}

// ======================================================================
// Kernel 0: W2 = W @ R (z=0), R2 = R @ R (z=1).  512x512x512 each.
// ======================================================================
__global__ __launch_bounds__(256) void prep_gemm(const float* __restrict__ W,
                                                 const float* __restrict__ Rm) {
    __shared__ float As[8][128];
    __shared__ float Bs[8][128];

    const float* A = (blockIdx.z == 0) ? W : Rm;
    const float* B = Rm;
    float* O = (blockIdx.z == 0) ? g_W2 : g_R2;

    const int tid = threadIdx.x;
    const int m0 = blockIdx.y * 128;
    const int n0 = blockIdx.x * 128;

    const int ar = tid >> 1;
    const int ac = (tid & 1) * 4;
    const int br = tid >> 5;
    const int bc = (tid & 31) * 4;
    const int tx = tid & 15;
    const int ty = tid >> 4;

    unsigned long long acc[8][4];
#pragma unroll
    for (int i = 0; i < 8; i++)
#pragma unroll
        for (int j = 0; j < 4; j++) acc[i][j] = 0ull;

    float4 xa = *reinterpret_cast<const float4*>(&A[(size_t)(m0 + ar) * ND + ac]);
    float4 wb = *reinterpret_cast<const float4*>(&B[(size_t)br * NU + n0 + bc]);

    const int KT = ND / 8;
    for (int kt = 0; kt < KT; kt++) {
        As[ac + 0][ar] = xa.x; As[ac + 1][ar] = xa.y;
        As[ac + 2][ar] = xa.z; As[ac + 3][ar] = xa.w;
        *reinterpret_cast<float4*>(&Bs[br][bc]) = wb;
        __syncthreads();
        if (kt + 1 < KT) {
            xa = *reinterpret_cast<const float4*>(&A[(size_t)(m0 + ar) * ND + (kt + 1) * 8 + ac]);
            wb = *reinterpret_cast<const float4*>(&B[(size_t)((kt + 1) * 8 + br) * NU + n0 + bc]);
        }
#pragma unroll
        for (int k = 0; k < 8; k++) {
            float4 a0 = *reinterpret_cast<const float4*>(&As[k][ty * 8]);
            float4 a1 = *reinterpret_cast<const float4*>(&As[k][ty * 8 + 4]);
            ulonglong2 bq0 = *reinterpret_cast<const ulonglong2*>(&Bs[k][tx * 8]);
            ulonglong2 bq1 = *reinterpret_cast<const ulonglong2*>(&Bs[k][tx * 8 + 4]);
            float av[8] = {a0.x, a0.y, a0.z, a0.w, a1.x, a1.y, a1.z, a1.w};
#pragma unroll
            for (int i = 0; i < 8; i++) {
                unsigned long long aa = pk2s(av[i]);
                fma2(acc[i][0], aa, bq0.x); fma2(acc[i][1], aa, bq0.y);
                fma2(acc[i][2], aa, bq1.x); fma2(acc[i][3], aa, bq1.y);
            }
        }
        __syncthreads();
    }
#pragma unroll
    for (int i = 0; i < 8; i++) {
        size_t row = (size_t)(m0 + ty * 8 + i);
        float2* op = reinterpret_cast<float2*>(&O[row * NU + n0 + tx * 8]);
        op[0] = upk2(acc[i][0]); op[1] = upk2(acc[i][1]);
        op[2] = upk2(acc[i][2]); op[3] = upk2(acc[i][3]);
    }
}

// ======================================================================
// Kernel 1: z = [x_t | x_{t-1}] @ [W ; W2]   (M=32768, K=1024)
// z_t = xw_t + xw_{t-1}@R ; rows with t==0 mask the second half to zero.
// ======================================================================
__device__ __forceinline__ float4 loadA_cat(const float* __restrict__ X, int m, int k) {
    if (k < ND) return *reinterpret_cast<const float4*>(&X[(size_t)m * ND + k]);
    if ((m & (NT - 1)) == 0) return make_float4(0.f, 0.f, 0.f, 0.f);
    return *reinterpret_cast<const float4*>(&X[(size_t)(m - 1) * ND + (k - ND)]);
}
__device__ __forceinline__ float4 loadB_cat(const float* __restrict__ W, int kk, int n) {
    if (kk < ND) return *reinterpret_cast<const float4*>(&W[(size_t)kk * NU + n]);
    return *reinterpret_cast<const float4*>(&g_W2[(size_t)(kk - ND) * NU + n]);
}

__global__ __launch_bounds__(256) void zcat_gemm(const float* __restrict__ X,
                                                 const float* __restrict__ W) {
    __shared__ float As[8][128];
    __shared__ float Bs[8][128];

    const int tid = threadIdx.x;
    const int m0 = blockIdx.y * 128;
    const int n0 = blockIdx.x * 128;

    const int ar = tid >> 1;
    const int ac = (tid & 1) * 4;
    const int br = tid >> 5;
    const int bc = (tid & 31) * 4;
    const int tx = tid & 15;
    const int ty = tid >> 4;

    unsigned long long acc[8][4];
#pragma unroll
    for (int i = 0; i < 8; i++)
#pragma unroll
        for (int j = 0; j < 4; j++) acc[i][j] = 0ull;

    float4 xa = loadA_cat(X, m0 + ar, ac);
    float4 wb = loadB_cat(W, br, n0 + bc);

    const int KT = (2 * ND) / 8;  // 128
    for (int kt = 0; kt < KT; kt++) {
        As[ac + 0][ar] = xa.x; As[ac + 1][ar] = xa.y;
        As[ac + 2][ar] = xa.z; As[ac + 3][ar] = xa.w;
        *reinterpret_cast<float4*>(&Bs[br][bc]) = wb;
        __syncthreads();
        if (kt + 1 < KT) {
            xa = loadA_cat(X, m0 + ar, (kt + 1) * 8 + ac);
            wb = loadB_cat(W, (kt + 1) * 8 + br, n0 + bc);
        }
#pragma unroll
        for (int k = 0; k < 8; k++) {
            float4 a0 = *reinterpret_cast<const float4*>(&As[k][ty * 8]);
            float4 a1 = *reinterpret_cast<const float4*>(&As[k][ty * 8 + 4]);
            ulonglong2 bq0 = *reinterpret_cast<const ulonglong2*>(&Bs[k][tx * 8]);
            ulonglong2 bq1 = *reinterpret_cast<const ulonglong2*>(&Bs[k][tx * 8 + 4]);
            float av[8] = {a0.x, a0.y, a0.z, a0.w, a1.x, a1.y, a1.z, a1.w};
#pragma unroll
            for (int i = 0; i < 8; i++) {
                unsigned long long aa = pk2s(av[i]);
                fma2(acc[i][0], aa, bq0.x); fma2(acc[i][1], aa, bq0.y);
                fma2(acc[i][2], aa, bq1.x); fma2(acc[i][3], aa, bq1.y);
            }
        }
        __syncthreads();
    }
#pragma unroll
    for (int i = 0; i < 8; i++) {
        size_t row = (size_t)(m0 + ty * 8 + i);
        float2* op = reinterpret_cast<float2*>(&g_z[row * NU + n0 + tx * 8]);
        op[0] = upk2(acc[i][0]); op[1] = upk2(acc[i][1]);
        op[2] = upk2(acc[i][2]); op[3] = upk2(acc[i][3]);
    }
}

// ======================================================================
// Kernel 2: lag-2 scan  h_t = z_t + h_{t-2} @ R2
// 16 clusters x 8 CTAs, R4's proven compute core. 4 h-slots / 4 barriers
// indexed by (chain=t&1, parity=(t>>1)&1): step t's comm has TWO steps
// to deliver -> sync round-trip comes off the critical path.
// ======================================================================
__global__ __launch_bounds__(256, 1) __cluster_dims__(8, 1, 1)
void scan_kernel(float* __restrict__ out) {
    __shared__ alignas(16) float hbuf[4][8][2][64];   // [slot][srcRank][batch][unit] 16KB
    __shared__ float red[16][2][4][16];               // [kb][b][j][q]                 8KB
    __shared__ alignas(8) unsigned long long mbar[2][2];  // [chain][parity]

    const int tid = threadIdx.x;
    uint32_t rank;
    asm("mov.u32 %0, %%cluster_ctarank;" : "=r"(rank));
    const int cluster = blockIdx.x >> 3;
    const int b0 = cluster * 2;
    const int useg = (int)rank * 64;

    const int q = tid & 15;                   // u-quad (16 quads = 64 units)
    const int kb = tid >> 4;                  // k block (16 blocks of 32)
    const int ug = useg + q * 4;
    const int k0 = kb * 32;

    // R2 slice as k-pairs: Rp[j][i] = {R2[k0+2i][ug+j], R2[k0+2i+1][ug+j]}
    unsigned long long Rp[4][16];
#pragma unroll
    for (int i = 0; i < 16; i++) {
        float4 v0 = *reinterpret_cast<const float4*>(&g_R2[(size_t)(k0 + 2 * i) * NU + ug]);
        float4 v1 = *reinterpret_cast<const float4*>(&g_R2[(size_t)(k0 + 2 * i + 1) * NU + ug]);
        Rp[0][i] = pk2(v0.x, v1.x);
        Rp[1][i] = pk2(v0.y, v1.y);
        Rp[2][i] = pk2(v0.z, v1.z);
        Rp[3][i] = pk2(v0.w, v1.w);
    }

    // zero all 4 h slots (steps 0,1 read zeros -> h = z exactly)
    for (int i = tid; i < 4 * 8 * 2 * 64; i += 256) (&hbuf[0][0][0][0])[i] = 0.f;

    uint32_t barL[2][2];
#pragma unroll
    for (int c = 0; c < 2; c++)
#pragma unroll
        for (int p = 0; p < 2; p++)
            barL[c][p] = (uint32_t)__cvta_generic_to_shared(&mbar[c][p]);
    if (tid == 0) {
#pragma unroll
        for (int c = 0; c < 2; c++)
#pragma unroll
            for (int p = 0; p < 2; p++) {
                asm volatile("mbarrier.init.shared.b64 [%0], 1;" :: "r"(barL[c][p]) : "memory");
                asm volatile("mbarrier.arrive.expect_tx.shared.b64 _, [%0], %1;"
                             :: "r"(barL[c][p]), "r"(3584) : "memory");  // 7 x 512B
            }
    }
    __syncthreads();
    // one-time rendezvous: inits/arms + zeroed hbuf visible before any bulk
    asm volatile("barrier.cluster.arrive.aligned;" ::: "memory");
    asm volatile("barrier.cluster.wait.aligned;" ::: "memory");

    // owner threads (tid<128): one (batch, unit) output each
    const bool owner = tid < 128;
    const int ob = tid >> 6;
    const int ou = tid & 63;
    const int oq = ou >> 2, oj = ou & 3;
    const float* zp = &g_z[((size_t)(b0 + ob) * NT) * NU + useg + ou];
    float* outp = &out[((size_t)(b0 + ob) * NT) * NU + useg + ou];
    float zcur = owner ? zp[0] : 0.f;

    // sender endpoint tables: tid 0..6 each own one destination CTA
    uint32_t srcA[4], dstA[4], mbR[4];
    if (tid < 7) {
        const int d = (tid < (int)rank) ? tid : tid + 1;
#pragma unroll
        for (int s = 0; s < 4; s++) {
            srcA[s] = (uint32_t)__cvta_generic_to_shared(&hbuf[s][rank][0][0]);
            asm("mapa.shared::cluster.u32 %0, %1, %2;"
                : "=r"(dstA[s]) : "r"(srcA[s]), "r"(d));
            asm("mapa.shared::cluster.u32 %0, %1, %2;"
                : "=r"(mbR[s]) : "r"(barL[s >> 1][s & 1]), "r"(d));
        }
    }

    int par4[2][2] = {{0, 0}, {0, 0}};

    for (int t = 0; t < NT; t++) {
        const int c = t & 1;
        const int p = (t >> 1) & 1;
        const int slot = c * 2 + p;            // holds h_{t-2}
        const int dslot = c * 2 + (p ^ 1);     // receives h_t (consumed at t+2)

        if (t >= 2) {
            const uint32_t ba = barL[c][p];
            const uint32_t ph = (uint32_t)par4[c][p];
            uint32_t done;
            asm volatile(
                "{\n\t.reg .pred p;\n\t"
                "mbarrier.try_wait.parity.acquire.cluster.shared::cta.b64 p, [%1], %2;\n\t"
                "selp.b32 %0, 1, 0, p;\n\t}"
                : "=r"(done) : "r"(ba), "r"(ph) : "memory");
            while (!done) {
                asm volatile(
                    "{\n\t.reg .pred p;\n\t"
                    "mbarrier.try_wait.parity.acquire.cluster.shared::cta.b64 p, [%1], %2, 0x989680;\n\t"
                    "selp.b32 %0, 1, 0, p;\n\t}"
                    : "=r"(done) : "r"(ba), "r"(ph) : "memory");
            }
            par4[c][p] ^= 1;
            // re-arm for t+4 (tid0's own sends at t follow in program order ->
            // causal: every peer's t+2 sends are gated by my t sends)
            if (tid == 0 && (t + 4) < NT) {
                asm volatile("mbarrier.arrive.expect_tx.shared.b64 _, [%0], %1;"
                             :: "r"(ba), "r"(3584) : "memory");
            }
        }

        // prefetch next z (hidden under FMA loop)
        float znxt = 0.f;
        if (owner && (t + 1) < NT) znxt = zp[(size_t)(t + 1) * NU];

        // ---- partial matvec h_{t-2}@R2 over this thread's 32-k block ----
        const float* h0 = &hbuf[slot][kb >> 1][0][(kb & 1) * 32];
        const float* h1 = &hbuf[slot][kb >> 1][1][(kb & 1) * 32];
        unsigned long long acc[2][4][2];
#pragma unroll
        for (int b = 0; b < 2; b++)
#pragma unroll
            for (int j = 0; j < 4; j++) { acc[b][j][0] = 0ull; acc[b][j][1] = 0ull; }

#pragma unroll
        for (int g = 0; g < 8; g++) {
            ulonglong2 hp0 = *reinterpret_cast<const ulonglong2*>(&h0[g * 4]);
            ulonglong2 hp1 = *reinterpret_cast<const ulonglong2*>(&h1[g * 4]);
#pragma unroll
            for (int j = 0; j < 4; j++) {
                fma2(acc[0][j][0], Rp[j][2 * g + 0], hp0.x);
                fma2(acc[0][j][1], Rp[j][2 * g + 1], hp0.y);
                fma2(acc[1][j][0], Rp[j][2 * g + 0], hp1.x);
                fma2(acc[1][j][1], Rp[j][2 * g + 1], hp1.y);
            }
        }

#pragma unroll
        for (int b = 0; b < 2; b++)
#pragma unroll
            for (int j = 0; j < 4; j++) {
                float2 s0 = upk2(acc[b][j][0]);
                float2 s1 = upk2(acc[b][j][1]);
                red[kb][b][j][q] = (s0.x + s0.y) + (s1.x + s1.y);
            }
        __syncthreads();   // all matvec reads + partials done (all 256 threads)

        if (tid < 128) {
            float s = 0.f;
#pragma unroll
            for (int r8 = 0; r8 < 16; r8++) s += red[r8][ob][oj][oq];
            const float val = zcur + s;
            outp[(size_t)t * NU] = val;

            if (t + 2 < NT) {
                hbuf[dslot][rank][ob][ou] = val;   // own slice, local
                asm volatile("bar.sync 1, 128;" ::: "memory");  // slice complete
                if (tid < 7) {
                    asm volatile("fence.proxy.async.shared::cta;" ::: "memory");
                    asm volatile(
                        "cp.async.bulk.shared::cluster.shared::cta.mbarrier::complete_tx::bytes "
                        "[%0], [%1], %2, [%3];"
                        :: "r"(dstA[dslot]), "r"(srcA[dslot]), "r"(512), "r"(mbR[dslot])
                        : "memory");
                }
            }
        }
        zcur = znxt;
    }

    // final rendezvous: no CTA exits while peers could still touch its smem
    asm volatile("barrier.cluster.arrive.aligned;" ::: "memory");
    asm volatile("barrier.cluster.wait.aligned;" ::: "memory");
}

// ======================================================================
extern "C" void kernel_launch(void* const* d_in, const int* in_sizes, int n_in,
                              void* d_out, int out_size) {
    const float* x = (const float*)d_in[0];            // [32,1024,512]
    const float* W = (const float*)d_in[1];            // kernel [512,512]
    const float* R = (const float*)d_in[2];            // recurrent_kernel [512,512]
    float* out = (float*)d_out;                        // [32,1024,512]

    prep_gemm<<<dim3(4, 4, 2), 256>>>(W, R);           // W2 = W@R, R2 = R@R
    dim3 gg(NU / 128, (NB * NT) / 128);                // (4, 256)
    zcat_gemm<<<gg, 256>>>(x, W);                      // z = x@W + xshift@W2
    scan_kernel<<<128, 256>>>(out);                    // lag-2 scan
}

// round 10
// speedup vs baseline: 1.4214x; 1.0132x over previous
#include <cuda_runtime.h>
#include <cstdint>

#define NB 32
#define NT 1024
#define ND 512
#define NU 512

// static scratch (no allocation): z = x@W + xshift@W2, plus W2=W@R, R2=R@R
__device__ float g_z[NB * NT * NU];     // 64MB
__device__ float g_W2[ND * NU];         // 1MB
__device__ float g_R2[NU * NU];         // 1MB

// ---------------- f32x2 packed helpers ----------------
__device__ __forceinline__ unsigned long long pk2(float x, float y) {
    unsigned long long r;
    asm("mov.b64 %0, {%1, %2};" : "=l"(r) : "f"(x), "f"(y));
    return r;
}
__device__ __forceinline__ unsigned long long pk2s(float x) {
    unsigned long long r;
    asm("mov.b64 %0, {%1, %1};" : "=l"(r) : "f"(x));
    return r;
}
__device__ __forceinline__ void fma2(unsigned long long& d, unsigned long long a,
                                     unsigned long long b) {
    asm("fma.rn.f32x2 %0, %1, %2, %0;" : "+l"(d) : "l"(a), "l"(b));
}
__device__ __forceinline__ float2 upk2(unsigned long long a) {
    float2 r;
    asm("mov.b64 {%0, %1}, %2;" : "=f"(r.x), "=f"(r.y) : "l"(a));
    return r;
}

// ======================================================================
// Kernel 0: W2 = W @ R (z=0), R2 = R @ R (z=1).  512x512x512 each.
// ======================================================================
__global__ __launch_bounds__(256) void prep_gemm(const float* __restrict__ W,
                                                 const float* __restrict__ Rm) {
    __shared__ float As[8][128];
    __shared__ float Bs[8][128];

    const float* A = (blockIdx.z == 0) ? W : Rm;
    const float* B = Rm;
    float* O = (blockIdx.z == 0) ? g_W2 : g_R2;

    const int tid = threadIdx.x;
    const int m0 = blockIdx.y * 128;
    const int n0 = blockIdx.x * 128;

    const int ar = tid >> 1;
    const int ac = (tid & 1) * 4;
    const int br = tid >> 5;
    const int bc = (tid & 31) * 4;
    const int tx = tid & 15;
    const int ty = tid >> 4;

    unsigned long long acc[8][4];
#pragma unroll
    for (int i = 0; i < 8; i++)
#pragma unroll
        for (int j = 0; j < 4; j++) acc[i][j] = 0ull;

    float4 xa = *reinterpret_cast<const float4*>(&A[(size_t)(m0 + ar) * ND + ac]);
    float4 wb = *reinterpret_cast<const float4*>(&B[(size_t)br * NU + n0 + bc]);

    const int KT = ND / 8;
    for (int kt = 0; kt < KT; kt++) {
        As[ac + 0][ar] = xa.x; As[ac + 1][ar] = xa.y;
        As[ac + 2][ar] = xa.z; As[ac + 3][ar] = xa.w;
        *reinterpret_cast<float4*>(&Bs[br][bc]) = wb;
        __syncthreads();
        if (kt + 1 < KT) {
            xa = *reinterpret_cast<const float4*>(&A[(size_t)(m0 + ar) * ND + (kt + 1) * 8 + ac]);
            wb = *reinterpret_cast<const float4*>(&B[(size_t)((kt + 1) * 8 + br) * NU + n0 + bc]);
        }
#pragma unroll
        for (int k = 0; k < 8; k++) {
            float4 a0 = *reinterpret_cast<const float4*>(&As[k][ty * 8]);
            float4 a1 = *reinterpret_cast<const float4*>(&As[k][ty * 8 + 4]);
            ulonglong2 bq0 = *reinterpret_cast<const ulonglong2*>(&Bs[k][tx * 8]);
            ulonglong2 bq1 = *reinterpret_cast<const ulonglong2*>(&Bs[k][tx * 8 + 4]);
            float av[8] = {a0.x, a0.y, a0.z, a0.w, a1.x, a1.y, a1.z, a1.w};
#pragma unroll
            for (int i = 0; i < 8; i++) {
                unsigned long long aa = pk2s(av[i]);
                fma2(acc[i][0], aa, bq0.x); fma2(acc[i][1], aa, bq0.y);
                fma2(acc[i][2], aa, bq1.x); fma2(acc[i][3], aa, bq1.y);
            }
        }
        __syncthreads();
    }
#pragma unroll
    for (int i = 0; i < 8; i++) {
        size_t row = (size_t)(m0 + ty * 8 + i);
        float2* op = reinterpret_cast<float2*>(&O[row * NU + n0 + tx * 8]);
        op[0] = upk2(acc[i][0]); op[1] = upk2(acc[i][1]);
        op[2] = upk2(acc[i][2]); op[3] = upk2(acc[i][3]);
    }
}

// ======================================================================
// Kernel 1: z = [x_t | x_{t-1}] @ [W ; W2]   (M=32768, K=1024)
// z_t = xw_t + xw_{t-1}@R ; rows with t==0 mask the second half to zero.
// ======================================================================
__device__ __forceinline__ float4 loadA_cat(const float* __restrict__ X, int m, int k) {
    if (k < ND) return *reinterpret_cast<const float4*>(&X[(size_t)m * ND + k]);
    if ((m & (NT - 1)) == 0) return make_float4(0.f, 0.f, 0.f, 0.f);
    return *reinterpret_cast<const float4*>(&X[(size_t)(m - 1) * ND + (k - ND)]);
}
__device__ __forceinline__ float4 loadB_cat(const float* __restrict__ W, int kk, int n) {
    if (kk < ND) return *reinterpret_cast<const float4*>(&W[(size_t)kk * NU + n]);
    return *reinterpret_cast<const float4*>(&g_W2[(size_t)(kk - ND) * NU + n]);
}

__global__ __launch_bounds__(256) void zcat_gemm(const float* __restrict__ X,
                                                 const float* __restrict__ W) {
    __shared__ float As[8][128];
    __shared__ float Bs[8][128];

    const int tid = threadIdx.x;
    const int m0 = blockIdx.y * 128;
    const int n0 = blockIdx.x * 128;

    const int ar = tid >> 1;
    const int ac = (tid & 1) * 4;
    const int br = tid >> 5;
    const int bc = (tid & 31) * 4;
    const int tx = tid & 15;
    const int ty = tid >> 4;

    unsigned long long acc[8][4];
#pragma unroll
    for (int i = 0; i < 8; i++)
#pragma unroll
        for (int j = 0; j < 4; j++) acc[i][j] = 0ull;

    float4 xa = loadA_cat(X, m0 + ar, ac);
    float4 wb = loadB_cat(W, br, n0 + bc);

    const int KT = (2 * ND) / 8;  // 128
    for (int kt = 0; kt < KT; kt++) {
        As[ac + 0][ar] = xa.x; As[ac + 1][ar] = xa.y;
        As[ac + 2][ar] = xa.z; As[ac + 3][ar] = xa.w;
        *reinterpret_cast<float4*>(&Bs[br][bc]) = wb;
        __syncthreads();
        if (kt + 1 < KT) {
            xa = loadA_cat(X, m0 + ar, (kt + 1) * 8 + ac);
            wb = loadB_cat(W, (kt + 1) * 8 + br, n0 + bc);
        }
#pragma unroll
        for (int k = 0; k < 8; k++) {
            float4 a0 = *reinterpret_cast<const float4*>(&As[k][ty * 8]);
            float4 a1 = *reinterpret_cast<const float4*>(&As[k][ty * 8 + 4]);
            ulonglong2 bq0 = *reinterpret_cast<const ulonglong2*>(&Bs[k][tx * 8]);
            ulonglong2 bq1 = *reinterpret_cast<const ulonglong2*>(&Bs[k][tx * 8 + 4]);
            float av[8] = {a0.x, a0.y, a0.z, a0.w, a1.x, a1.y, a1.z, a1.w};
#pragma unroll
            for (int i = 0; i < 8; i++) {
                unsigned long long aa = pk2s(av[i]);
                fma2(acc[i][0], aa, bq0.x); fma2(acc[i][1], aa, bq0.y);
                fma2(acc[i][2], aa, bq1.x); fma2(acc[i][3], aa, bq1.y);
            }
        }
        __syncthreads();
    }
#pragma unroll
    for (int i = 0; i < 8; i++) {
        size_t row = (size_t)(m0 + ty * 8 + i);
        float2* op = reinterpret_cast<float2*>(&g_z[row * NU + n0 + tx * 8]);
        op[0] = upk2(acc[i][0]); op[1] = upk2(acc[i][1]);
        op[2] = upk2(acc[i][2]); op[3] = upk2(acc[i][3]);
    }
}

// ======================================================================
// Kernel 2: lag-2 scan  h_t = z_t + h_{t-2} @ R2
// 16 clusters x 8 CTAs. Dual (chain,parity) mbarriers + aggregated DSMEM
// bulk copies. THIS ROUND: cta-scope acquire on the mbarrier wait (the
// cluster-scope acquire costs ~490 cyc/step; cta scope suffices because
// the bulk's complete_tx tracks the async writes into OUR smem), and a
// conflict-free reduction layout red[kb][b][q][j] with STS.128 partials.
// ======================================================================
__global__ __launch_bounds__(256, 1) __cluster_dims__(8, 1, 1)
void scan_kernel(float* __restrict__ out) {
    __shared__ alignas(16) float hbuf[4][8][2][64];   // [slot][srcRank][batch][unit] 16KB
    __shared__ alignas(16) float red[16][2][16][4];   // [kb][b][q][j]                 8KB
    __shared__ alignas(8) unsigned long long mbar[2][2];  // [chain][parity]

    const int tid = threadIdx.x;
    uint32_t rank;
    asm("mov.u32 %0, %%cluster_ctarank;" : "=r"(rank));
    const int cluster = blockIdx.x >> 3;
    const int b0 = cluster * 2;
    const int useg = (int)rank * 64;

    const int q = tid & 15;                   // u-quad (16 quads = 64 units)
    const int kb = tid >> 4;                  // k block (16 blocks of 32)
    const int ug = useg + q * 4;
    const int k0 = kb * 32;

    // R2 slice as k-pairs: Rp[j][i] = {R2[k0+2i][ug+j], R2[k0+2i+1][ug+j]}
    unsigned long long Rp[4][16];
#pragma unroll
    for (int i = 0; i < 16; i++) {
        float4 v0 = *reinterpret_cast<const float4*>(&g_R2[(size_t)(k0 + 2 * i) * NU + ug]);
        float4 v1 = *reinterpret_cast<const float4*>(&g_R2[(size_t)(k0 + 2 * i + 1) * NU + ug]);
        Rp[0][i] = pk2(v0.x, v1.x);
        Rp[1][i] = pk2(v0.y, v1.y);
        Rp[2][i] = pk2(v0.z, v1.z);
        Rp[3][i] = pk2(v0.w, v1.w);
    }

    // zero all 4 h slots (steps 0,1 read zeros -> h = z exactly)
    for (int i = tid; i < 4 * 8 * 2 * 64; i += 256) (&hbuf[0][0][0][0])[i] = 0.f;

    uint32_t barL[2][2];
#pragma unroll
    for (int c = 0; c < 2; c++)
#pragma unroll
        for (int p = 0; p < 2; p++)
            barL[c][p] = (uint32_t)__cvta_generic_to_shared(&mbar[c][p]);
    if (tid == 0) {
#pragma unroll
        for (int c = 0; c < 2; c++)
#pragma unroll
            for (int p = 0; p < 2; p++) {
                asm volatile("mbarrier.init.shared.b64 [%0], 1;" :: "r"(barL[c][p]) : "memory");
                asm volatile("mbarrier.arrive.expect_tx.shared.b64 _, [%0], %1;"
                             :: "r"(barL[c][p]), "r"(3584) : "memory");  // 7 x 512B
            }
    }
    __syncthreads();
    // one-time rendezvous: inits/arms + zeroed hbuf visible before any bulk
    asm volatile("barrier.cluster.arrive.aligned;" ::: "memory");
    asm volatile("barrier.cluster.wait.aligned;" ::: "memory");

    // owner threads (tid<128): one (batch, unit) output each
    const bool owner = tid < 128;
    const int ob = tid >> 6;
    const int ou = tid & 63;
    const int oq = ou >> 2, oj = ou & 3;
    const float* zp = &g_z[((size_t)(b0 + ob) * NT) * NU + useg + ou];
    float* outp = &out[((size_t)(b0 + ob) * NT) * NU + useg + ou];
    float zcur = owner ? zp[0] : 0.f;

    // sender endpoint tables: tid 0..6 each own one destination CTA
    uint32_t srcA[4], dstA[4], mbR[4];
    if (tid < 7) {
        const int d = (tid < (int)rank) ? tid : tid + 1;
#pragma unroll
        for (int s = 0; s < 4; s++) {
            srcA[s] = (uint32_t)__cvta_generic_to_shared(&hbuf[s][rank][0][0]);
            asm("mapa.shared::cluster.u32 %0, %1, %2;"
                : "=r"(dstA[s]) : "r"(srcA[s]), "r"(d));
            asm("mapa.shared::cluster.u32 %0, %1, %2;"
                : "=r"(mbR[s]) : "r"(barL[s >> 1][s & 1]), "r"(d));
        }
    }

    int par4[2][2] = {{0, 0}, {0, 0}};

    for (int t = 0; t < NT; t++) {
        const int c = t & 1;
        const int p = (t >> 1) & 1;
        const int slot = c * 2 + p;            // holds h_{t-2}
        const int dslot = c * 2 + (p ^ 1);     // receives h_t (consumed at t+2)

        if (t >= 2) {
            const uint32_t ba = barL[c][p];
            const uint32_t ph = (uint32_t)par4[c][p];
            uint32_t done;
            asm volatile(
                "{\n\t.reg .pred p;\n\t"
                "mbarrier.try_wait.parity.acquire.cta.shared::cta.b64 p, [%1], %2;\n\t"
                "selp.b32 %0, 1, 0, p;\n\t}"
                : "=r"(done) : "r"(ba), "r"(ph) : "memory");
            while (!done) {
                asm volatile(
                    "{\n\t.reg .pred p;\n\t"
                    "mbarrier.try_wait.parity.acquire.cta.shared::cta.b64 p, [%1], %2, 0x989680;\n\t"
                    "selp.b32 %0, 1, 0, p;\n\t}"
                    : "=r"(done) : "r"(ba), "r"(ph) : "memory");
            }
            par4[c][p] ^= 1;
            // re-arm for t+4 (tid0's own sends at t follow in program order ->
            // causal: every peer's t+2 sends are gated by my t sends)
            if (tid == 0 && (t + 4) < NT) {
                asm volatile("mbarrier.arrive.expect_tx.shared.b64 _, [%0], %1;"
                             :: "r"(ba), "r"(3584) : "memory");
            }
        }

        // prefetch next z (hidden under FMA loop)
        float znxt = 0.f;
        if (owner && (t + 1) < NT) znxt = zp[(size_t)(t + 1) * NU];

        // ---- partial matvec h_{t-2}@R2 over this thread's 32-k block ----
        const float* h0 = &hbuf[slot][kb >> 1][0][(kb & 1) * 32];
        const float* h1 = &hbuf[slot][kb >> 1][1][(kb & 1) * 32];
        unsigned long long acc[2][4][2];
#pragma unroll
        for (int b = 0; b < 2; b++)
#pragma unroll
            for (int j = 0; j < 4; j++) { acc[b][j][0] = 0ull; acc[b][j][1] = 0ull; }

#pragma unroll
        for (int g = 0; g < 8; g++) {
            ulonglong2 hp0 = *reinterpret_cast<const ulonglong2*>(&h0[g * 4]);
            ulonglong2 hp1 = *reinterpret_cast<const ulonglong2*>(&h1[g * 4]);
#pragma unroll
            for (int j = 0; j < 4; j++) {
                fma2(acc[0][j][0], Rp[j][2 * g + 0], hp0.x);
                fma2(acc[0][j][1], Rp[j][2 * g + 1], hp0.y);
                fma2(acc[1][j][0], Rp[j][2 * g + 0], hp1.x);
                fma2(acc[1][j][1], Rp[j][2 * g + 1], hp1.y);
            }
        }

        // ---- stash partials: one STS.128 per batch, conflict-free ----
#pragma unroll
        for (int b = 0; b < 2; b++) {
            float pj[4];
#pragma unroll
            for (int j = 0; j < 4; j++) {
                float2 s0 = upk2(acc[b][j][0]);
                float2 s1 = upk2(acc[b][j][1]);
                pj[j] = (s0.x + s0.y) + (s1.x + s1.y);
            }
            *reinterpret_cast<float4*>(&red[kb][b][q][0]) =
                make_float4(pj[0], pj[1], pj[2], pj[3]);
        }
        __syncthreads();   // all matvec reads + partials done (all 256 threads)

        if (tid < 128) {
            float s = 0.f;
#pragma unroll
            for (int r8 = 0; r8 < 16; r8++) s += red[r8][ob][oq][oj];
            const float val = zcur + s;
            outp[(size_t)t * NU] = val;

            if (t + 2 < NT) {
                hbuf[dslot][rank][ob][ou] = val;   // own slice, local
                asm volatile("bar.sync 1, 128;" ::: "memory");  // slice complete
                if (tid < 7) {
                    asm volatile("fence.proxy.async.shared::cta;" ::: "memory");
                    asm volatile(
                        "cp.async.bulk.shared::cluster.shared::cta.mbarrier::complete_tx::bytes "
                        "[%0], [%1], %2, [%3];"
                        :: "r"(dstA[dslot]), "r"(srcA[dslot]), "r"(512), "r"(mbR[dslot])
                        : "memory");
                }
            }
        }
        zcur = znxt;
    }

    // final rendezvous: no CTA exits while peers could still touch its smem
    asm volatile("barrier.cluster.arrive.aligned;" ::: "memory");
    asm volatile("barrier.cluster.wait.aligned;" ::: "memory");
}

// ======================================================================
extern "C" void kernel_launch(void* const* d_in, const int* in_sizes, int n_in,
                              void* d_out, int out_size) {
    const float* x = (const float*)d_in[0];            // [32,1024,512]
    const float* W = (const float*)d_in[1];            // kernel [512,512]
    const float* R = (const float*)d_in[2];            // recurrent_kernel [512,512]
    float* out = (float*)d_out;                        // [32,1024,512]

    prep_gemm<<<dim3(4, 4, 2), 256>>>(W, R);           // W2 = W@R, R2 = R@R
    dim3 gg(NU / 128, (NB * NT) / 128);                // (4, 256)
    zcat_gemm<<<gg, 256>>>(x, W);                      // z = x@W + xshift@W2
    scan_kernel<<<128, 256>>>(out);                    // lag-2 scan
}

// round 11
// speedup vs baseline: 1.5203x; 1.0696x over previous
#include <cuda_runtime.h>
#include <cstdint>

#define NB 32
#define NT 1024
#define ND 512
#define NU 512
#define NR (NT / 2)   // rounds: 2 steps (chains) per round

// static scratch (no allocation): z = x@W + xshift@W2, plus W2=W@R, R2=R@R
__device__ float g_z[NB * NT * NU];     // 64MB
__device__ float g_W2[ND * NU];         // 1MB
__device__ float g_R2[NU * NU];         // 1MB

// ---------------- f32x2 packed helpers ----------------
__device__ __forceinline__ unsigned long long pk2(float x, float y) {
    unsigned long long r;
    asm("mov.b64 %0, {%1, %2};" : "=l"(r) : "f"(x), "f"(y));
    return r;
}
__device__ __forceinline__ unsigned long long pk2s(float x) {
    unsigned long long r;
    asm("mov.b64 %0, {%1, %1};" : "=l"(r) : "f"(x));
    return r;
}
__device__ __forceinline__ void fma2(unsigned long long& d, unsigned long long a,
                                     unsigned long long b) {
    asm("fma.rn.f32x2 %0, %1, %2, %0;" : "+l"(d) : "l"(a), "l"(b));
}
__device__ __forceinline__ float2 upk2(unsigned long long a) {
    float2 r;
    asm("mov.b64 {%0, %1}, %2;" : "=f"(r.x), "=f"(r.y) : "l"(a));
    return r;
}

// ======================================================================
// Kernel 0: W2 = W @ R (z=0), R2 = R @ R (z=1).  512x512x512 each.
// ======================================================================
__global__ __launch_bounds__(256) void prep_gemm(const float* __restrict__ W,
                                                 const float* __restrict__ Rm) {
    __shared__ float As[8][128];
    __shared__ float Bs[8][128];

    const float* A = (blockIdx.z == 0) ? W : Rm;
    const float* B = Rm;
    float* O = (blockIdx.z == 0) ? g_W2 : g_R2;

    const int tid = threadIdx.x;
    const int m0 = blockIdx.y * 128;
    const int n0 = blockIdx.x * 128;

    const int ar = tid >> 1;
    const int ac = (tid & 1) * 4;
    const int br = tid >> 5;
    const int bc = (tid & 31) * 4;
    const int tx = tid & 15;
    const int ty = tid >> 4;

    unsigned long long acc[8][4];
#pragma unroll
    for (int i = 0; i < 8; i++)
#pragma unroll
        for (int j = 0; j < 4; j++) acc[i][j] = 0ull;

    float4 xa = *reinterpret_cast<const float4*>(&A[(size_t)(m0 + ar) * ND + ac]);
    float4 wb = *reinterpret_cast<const float4*>(&B[(size_t)br * NU + n0 + bc]);

    const int KT = ND / 8;
    for (int kt = 0; kt < KT; kt++) {
        As[ac + 0][ar] = xa.x; As[ac + 1][ar] = xa.y;
        As[ac + 2][ar] = xa.z; As[ac + 3][ar] = xa.w;
        *reinterpret_cast<float4*>(&Bs[br][bc]) = wb;
        __syncthreads();
        if (kt + 1 < KT) {
            xa = *reinterpret_cast<const float4*>(&A[(size_t)(m0 + ar) * ND + (kt + 1) * 8 + ac]);
            wb = *reinterpret_cast<const float4*>(&B[(size_t)((kt + 1) * 8 + br) * NU + n0 + bc]);
        }
#pragma unroll
        for (int k = 0; k < 8; k++) {
            float4 a0 = *reinterpret_cast<const float4*>(&As[k][ty * 8]);
            float4 a1 = *reinterpret_cast<const float4*>(&As[k][ty * 8 + 4]);
            ulonglong2 bq0 = *reinterpret_cast<const ulonglong2*>(&Bs[k][tx * 8]);
            ulonglong2 bq1 = *reinterpret_cast<const ulonglong2*>(&Bs[k][tx * 8 + 4]);
            float av[8] = {a0.x, a0.y, a0.z, a0.w, a1.x, a1.y, a1.z, a1.w};
#pragma unroll
            for (int i = 0; i < 8; i++) {
                unsigned long long aa = pk2s(av[i]);
                fma2(acc[i][0], aa, bq0.x); fma2(acc[i][1], aa, bq0.y);
                fma2(acc[i][2], aa, bq1.x); fma2(acc[i][3], aa, bq1.y);
            }
        }
        __syncthreads();
    }
#pragma unroll
    for (int i = 0; i < 8; i++) {
        size_t row = (size_t)(m0 + ty * 8 + i);
        float2* op = reinterpret_cast<float2*>(&O[row * NU + n0 + tx * 8]);
        op[0] = upk2(acc[i][0]); op[1] = upk2(acc[i][1]);
        op[2] = upk2(acc[i][2]); op[3] = upk2(acc[i][3]);
    }
}

// ======================================================================
// Kernel 1: z = [x_t | x_{t-1}] @ [W ; W2]   (M=32768, K=1024)
// z_t = xw_t + xw_{t-1}@R ; rows with t==0 mask the second half to zero.
// ======================================================================
__device__ __forceinline__ float4 loadA_cat(const float* __restrict__ X, int m, int k) {
    if (k < ND) return *reinterpret_cast<const float4*>(&X[(size_t)m * ND + k]);
    if ((m & (NT - 1)) == 0) return make_float4(0.f, 0.f, 0.f, 0.f);
    return *reinterpret_cast<const float4*>(&X[(size_t)(m - 1) * ND + (k - ND)]);
}
__device__ __forceinline__ float4 loadB_cat(const float* __restrict__ W, int kk, int n) {
    if (kk < ND) return *reinterpret_cast<const float4*>(&W[(size_t)kk * NU + n]);
    return *reinterpret_cast<const float4*>(&g_W2[(size_t)(kk - ND) * NU + n]);
}

__global__ __launch_bounds__(256) void zcat_gemm(const float* __restrict__ X,
                                                 const float* __restrict__ W) {
    __shared__ float As[8][128];
    __shared__ float Bs[8][128];

    const int tid = threadIdx.x;
    const int m0 = blockIdx.y * 128;
    const int n0 = blockIdx.x * 128;

    const int ar = tid >> 1;
    const int ac = (tid & 1) * 4;
    const int br = tid >> 5;
    const int bc = (tid & 31) * 4;
    const int tx = tid & 15;
    const int ty = tid >> 4;

    unsigned long long acc[8][4];
#pragma unroll
    for (int i = 0; i < 8; i++)
#pragma unroll
        for (int j = 0; j < 4; j++) acc[i][j] = 0ull;

    float4 xa = loadA_cat(X, m0 + ar, ac);
    float4 wb = loadB_cat(W, br, n0 + bc);

    const int KT = (2 * ND) / 8;  // 128
    for (int kt = 0; kt < KT; kt++) {
        As[ac + 0][ar] = xa.x; As[ac + 1][ar] = xa.y;
        As[ac + 2][ar] = xa.z; As[ac + 3][ar] = xa.w;
        *reinterpret_cast<float4*>(&Bs[br][bc]) = wb;
        __syncthreads();
        if (kt + 1 < KT) {
            xa = loadA_cat(X, m0 + ar, (kt + 1) * 8 + ac);
            wb = loadB_cat(W, (kt + 1) * 8 + br, n0 + bc);
        }
#pragma unroll
        for (int k = 0; k < 8; k++) {
            float4 a0 = *reinterpret_cast<const float4*>(&As[k][ty * 8]);
            float4 a1 = *reinterpret_cast<const float4*>(&As[k][ty * 8 + 4]);
            ulonglong2 bq0 = *reinterpret_cast<const ulonglong2*>(&Bs[k][tx * 8]);
            ulonglong2 bq1 = *reinterpret_cast<const ulonglong2*>(&Bs[k][tx * 8 + 4]);
            float av[8] = {a0.x, a0.y, a0.z, a0.w, a1.x, a1.y, a1.z, a1.w};
#pragma unroll
            for (int i = 0; i < 8; i++) {
                unsigned long long aa = pk2s(av[i]);
                fma2(acc[i][0], aa, bq0.x); fma2(acc[i][1], aa, bq0.y);
                fma2(acc[i][2], aa, bq1.x); fma2(acc[i][3], aa, bq1.y);
            }
        }
        __syncthreads();
    }
#pragma unroll
    for (int i = 0; i < 8; i++) {
        size_t row = (size_t)(m0 + ty * 8 + i);
        float2* op = reinterpret_cast<float2*>(&g_z[row * NU + n0 + tx * 8]);
        op[0] = upk2(acc[i][0]); op[1] = upk2(acc[i][1]);
        op[2] = upk2(acc[i][2]); op[3] = upk2(acc[i][3]);
    }
}

// ======================================================================
// Kernel 2: lag-2 scan, BATCHED ROUNDS: round r computes h_{2r} and
// h_{2r+1} (both chains) with ONE wait / ONE syncthreads / ONE reduce /
// ONE send phase (7 x 1KB bulks, single barrier per parity). The per-step
// serial scaffolding is amortized 2x. 16 clusters x 8 CTAs.
// ======================================================================
__global__ __launch_bounds__(256, 1) __cluster_dims__(8, 1, 1)
void scan_kernel(float* __restrict__ out) {
    __shared__ alignas(16) float hbuf[2][8][2][2][64];  // [par][srcRank][chain][batch][unit] 16KB
    __shared__ alignas(16) float red[2][16][2][16][4];  // [chain][kb][b][q][j]               16KB
    __shared__ alignas(8) unsigned long long mbar[2];   // [parity]

    const int tid = threadIdx.x;
    uint32_t rank;
    asm("mov.u32 %0, %%cluster_ctarank;" : "=r"(rank));
    const int cluster = blockIdx.x >> 3;
    const int b0 = cluster * 2;
    const int useg = (int)rank * 64;

    const int q = tid & 15;                   // u-quad (16 quads = 64 units)
    const int kb = tid >> 4;                  // k block (16 blocks of 32)
    const int ug = useg + q * 4;
    const int k0 = kb * 32;

    // R2 slice as k-pairs: Rp[j][i] = {R2[k0+2i][ug+j], R2[k0+2i+1][ug+j]}
    unsigned long long Rp[4][16];
#pragma unroll
    for (int i = 0; i < 16; i++) {
        float4 v0 = *reinterpret_cast<const float4*>(&g_R2[(size_t)(k0 + 2 * i) * NU + ug]);
        float4 v1 = *reinterpret_cast<const float4*>(&g_R2[(size_t)(k0 + 2 * i + 1) * NU + ug]);
        Rp[0][i] = pk2(v0.x, v1.x);
        Rp[1][i] = pk2(v0.y, v1.y);
        Rp[2][i] = pk2(v0.z, v1.z);
        Rp[3][i] = pk2(v0.w, v1.w);
    }

    // zero both h parities (round 0 reads parity 0 = zeros -> h = z)
    for (int i = tid; i < 2 * 8 * 2 * 2 * 64; i += 256) (&hbuf[0][0][0][0][0])[i] = 0.f;

    uint32_t barL[2];
#pragma unroll
    for (int p = 0; p < 2; p++)
        barL[p] = (uint32_t)__cvta_generic_to_shared(&mbar[p]);
    if (tid == 0) {
#pragma unroll
        for (int p = 0; p < 2; p++) {
            asm volatile("mbarrier.init.shared.b64 [%0], 1;" :: "r"(barL[p]) : "memory");
            asm volatile("mbarrier.arrive.expect_tx.shared.b64 _, [%0], %1;"
                         :: "r"(barL[p]), "r"(7168) : "memory");  // 7 x 1024B
        }
    }
    __syncthreads();
    // one-time rendezvous: inits/arms + zeroed hbuf visible before any bulk
    asm volatile("barrier.cluster.arrive.aligned;" ::: "memory");
    asm volatile("barrier.cluster.wait.aligned;" ::: "memory");

    // owner threads (tid<128): one (batch, unit) output each, both chains
    const bool owner = tid < 128;
    const int ob = tid >> 6;
    const int ou = tid & 63;
    const int oq = ou >> 2, oj = ou & 3;
    const float* zbase = &g_z[((size_t)(b0 + ob) * NT) * NU + useg + ou];
    float* obase = &out[((size_t)(b0 + ob) * NT) * NU + useg + ou];
    float zcur[2];
    zcur[0] = owner ? zbase[0] : 0.f;              // t = 0
    zcur[1] = owner ? zbase[(size_t)NU] : 0.f;     // t = 1

    // sender endpoint tables (tid 0..6, one dest CTA each), per write-parity
    uint32_t srcA[2], dstA[2], mbR[2];
    if (tid < 7) {
        const int d = (tid < (int)rank) ? tid : tid + 1;
#pragma unroll
        for (int wp = 0; wp < 2; wp++) {
            srcA[wp] = (uint32_t)__cvta_generic_to_shared(&hbuf[wp][rank][0][0][0]);
            asm("mapa.shared::cluster.u32 %0, %1, %2;"
                : "=r"(dstA[wp]) : "r"(srcA[wp]), "r"(d));
            asm("mapa.shared::cluster.u32 %0, %1, %2;"
                : "=r"(mbR[wp]) : "r"(barL[wp]), "r"(d));
        }
    }

    int par2[2] = {0, 0};

    for (int r = 0; r < NR; r++) {
        const int p = r & 1;          // read parity
        const int wp = p ^ 1;         // write parity (consumed at round r+1)

        if (r >= 1) {
            const uint32_t ba = barL[p];
            const uint32_t ph = (uint32_t)par2[p];
            uint32_t done;
            asm volatile(
                "{\n\t.reg .pred p;\n\t"
                "mbarrier.try_wait.parity.acquire.cta.shared::cta.b64 p, [%1], %2;\n\t"
                "selp.b32 %0, 1, 0, p;\n\t}"
                : "=r"(done) : "r"(ba), "r"(ph) : "memory");
            while (!done) {
                asm volatile(
                    "{\n\t.reg .pred p;\n\t"
                    "mbarrier.try_wait.parity.acquire.cta.shared::cta.b64 p, [%1], %2, 0x989680;\n\t"
                    "selp.b32 %0, 1, 0, p;\n\t}"
                    : "=r"(done) : "r"(ba), "r"(ph) : "memory");
            }
            par2[p] ^= 1;
            // re-arm for round r+2 (tid0's own sends at r follow in program
            // order -> peers' r+1 sends are gated by my r sends -> causal)
            if (tid == 0 && (r + 2) < NR) {
                asm volatile("mbarrier.arrive.expect_tx.shared.b64 _, [%0], %1;"
                             :: "r"(ba), "r"(7168) : "memory");
            }
        }
        // ONE barrier per round: orders owners' round-(r-1) LOCAL staging
        // stores before all warps' reads this round (bulk arrivals are
        // ordered by the mbarrier; local stores need this).
        __syncthreads();

        // prefetch z for round r+1 (consumed next round -> full round to land)
        float znxt[2] = {0.f, 0.f};
        if (owner && (r + 1) < NR) {
            znxt[0] = zbase[(size_t)(2 * (r + 1) + 0) * NU];
            znxt[1] = zbase[(size_t)(2 * (r + 1) + 1) * NU];
        }

        // ---- matvec both chains, accumulators reused (reg pressure flat) ----
#pragma unroll
        for (int c = 0; c < 2; c++) {
            const float* h0 = &hbuf[p][kb >> 1][c][0][(kb & 1) * 32];
            const float* h1 = &hbuf[p][kb >> 1][c][1][(kb & 1) * 32];
            unsigned long long acc[2][4][2];
#pragma unroll
            for (int b = 0; b < 2; b++)
#pragma unroll
                for (int j = 0; j < 4; j++) { acc[b][j][0] = 0ull; acc[b][j][1] = 0ull; }

#pragma unroll
            for (int g = 0; g < 8; g++) {
                ulonglong2 hp0 = *reinterpret_cast<const ulonglong2*>(&h0[g * 4]);
                ulonglong2 hp1 = *reinterpret_cast<const ulonglong2*>(&h1[g * 4]);
#pragma unroll
                for (int j = 0; j < 4; j++) {
                    fma2(acc[0][j][0], Rp[j][2 * g + 0], hp0.x);
                    fma2(acc[0][j][1], Rp[j][2 * g + 1], hp0.y);
                    fma2(acc[1][j][0], Rp[j][2 * g + 0], hp1.x);
                    fma2(acc[1][j][1], Rp[j][2 * g + 1], hp1.y);
                }
            }
            // stash partials: one STS.128 per batch
#pragma unroll
            for (int b = 0; b < 2; b++) {
                float pj[4];
#pragma unroll
                for (int j = 0; j < 4; j++) {
                    float2 s0 = upk2(acc[b][j][0]);
                    float2 s1 = upk2(acc[b][j][1]);
                    pj[j] = (s0.x + s0.y) + (s1.x + s1.y);
                }
                *reinterpret_cast<float4*>(&red[c][kb][b][q][0]) =
                    make_float4(pj[0], pj[1], pj[2], pj[3]);
            }
        }
        __syncthreads();   // all partials staged (all 256 threads)

        if (owner) {
            float val[2];
#pragma unroll
            for (int c = 0; c < 2; c++) {
                float s = 0.f;
#pragma unroll
                for (int r8 = 0; r8 < 16; r8++) s += red[c][r8][ob][oq][oj];
                val[c] = zcur[c] + s;
                obase[(size_t)(2 * r + c) * NU] = val[c];
            }
            if (r + 1 < NR) {
                hbuf[wp][rank][0][ob][ou] = val[0];   // local staging (own slice)
                hbuf[wp][rank][1][ob][ou] = val[1];
                asm volatile("bar.sync 1, 128;" ::: "memory");  // slice complete
                if (tid < 7) {
                    asm volatile("fence.proxy.async.shared::cta;" ::: "memory");
                    asm volatile(
                        "cp.async.bulk.shared::cluster.shared::cta.mbarrier::complete_tx::bytes "
                        "[%0], [%1], %2, [%3];"
                        :: "r"(dstA[wp]), "r"(srcA[wp]), "r"(1024), "r"(mbR[wp])
                        : "memory");
                }
            }
        }
        zcur[0] = znxt[0];
        zcur[1] = znxt[1];
    }

    // final rendezvous: no CTA exits while peers could still touch its smem
    asm volatile("barrier.cluster.arrive.aligned;" ::: "memory");
    asm volatile("barrier.cluster.wait.aligned;" ::: "memory");
}

// ======================================================================
extern "C" void kernel_launch(void* const* d_in, const int* in_sizes, int n_in,
                              void* d_out, int out_size) {
    const float* x = (const float*)d_in[0];            // [32,1024,512]
    const float* W = (const float*)d_in[1];            // kernel [512,512]
    const float* R = (const float*)d_in[2];            // recurrent_kernel [512,512]
    float* out = (float*)d_out;                        // [32,1024,512]

    prep_gemm<<<dim3(4, 4, 2), 256>>>(W, R);           // W2 = W@R, R2 = R@R
    dim3 gg(NU / 128, (NB * NT) / 128);                // (4, 256)
    zcat_gemm<<<gg, 256>>>(x, W);                      // z = x@W + xshift@W2
    scan_kernel<<<128, 256>>>(out);                    // batched-round lag-2 scan
}